// round 15
// baseline (speedup 1.0000x reference)
#include <cuda_runtime.h>
#include <cuda_fp16.h>
#include <stdint.h>

#define B_DIM 64
#define C_DIM 128
#define HW_DIM 16384
#define L_DIM 50
#define TILES_PER_CTA 8
#define TILE_PX 128

// shared memory: fragment images only (u32 units)
#define KF_OFF32  0                        // 1792 uint2 = 3584 u32
#define VF2_OFF32 3584                     // 1536 uint2 = 3072 u32
#define VF3_OFF32 6656                     // 512 u32
#define SMEM_U32  7168
#define SMEM_BYTES (SMEM_U32 * 4)          // 28672 (3 CTAs: 86 KB/SM, fits)

static __device__ __align__(16) uint2    g_kfrag2[1792];  // 8 ks x 7 nt x 32 (fp16)
static __device__ __align__(16) uint2    g_vfrag2[1536];  // 3 ks x 16 nt x 32 (fp16)
static __device__ __align__(16) uint32_t g_vfrag3[512];   // 16 nt x 32 (ks=3 r0)

// ---------------------------------------------------------------- helpers
__device__ __forceinline__ uint32_t packhf(float lo, float hi) {
    __half2 t = __floats2half2_rn(lo, hi);
    return *(uint32_t*)&t;
}
__device__ __forceinline__ void split2h(float a, float b, uint32_t& hi, uint32_t& lo) {
    __half ha = __float2half_rn(a);
    __half hb = __float2half_rn(b);
    hi = ((uint32_t)__half_as_ushort(hb) << 16) | (uint32_t)__half_as_ushort(ha);
    lo = packhf(a - __half2float(ha), b - __half2float(hb));
}
__device__ __forceinline__ void mma_f16(float* d, const uint32_t* a,
                                        const uint32_t* b, const float* c) {
    asm volatile(
        "mma.sync.aligned.m16n8k16.row.col.f32.f16.f16.f32 "
        "{%0,%1,%2,%3}, {%4,%5,%6,%7}, {%8,%9}, {%10,%11,%12,%13};"
        : "=f"(d[0]), "=f"(d[1]), "=f"(d[2]), "=f"(d[3])
        : "r"(a[0]), "r"(a[1]), "r"(a[2]), "r"(a[3]),
          "r"(b[0]), "r"(b[1]),
          "f"(c[0]), "f"(c[1]), "f"(c[2]), "f"(c[3]));
}
__device__ __forceinline__ void mma_f16_k8(float* d, uint32_t a0, uint32_t a1,
                                           uint32_t b0, const float* c) {
    asm volatile(
        "mma.sync.aligned.m16n8k8.row.col.f32.f16.f16.f32 "
        "{%0,%1,%2,%3}, {%4,%5}, {%6}, {%7,%8,%9,%10};"
        : "=f"(d[0]), "=f"(d[1]), "=f"(d[2]), "=f"(d[3])
        : "r"(a0), "r"(a1), "r"(b0),
          "f"(c[0]), "f"(c[1]), "f"(c[2]), "f"(c[3]));
}

// ---------------------------------------------------- prep (fp16 images)
__global__ void prep_kernel(const float* __restrict__ keys,
                            const float* __restrict__ values) {
    __shared__ float knorm[64];
    int tid = threadIdx.x;
    if (tid < 64) {
        float s = 0.f;
        if (tid < L_DIM) {
            for (int c = 0; c < C_DIM; c++) {
                float v = keys[tid * C_DIM + c];
                s += v * v;
            }
        }
        knorm[tid] = (tid < L_DIM) ? rsqrtf(fmaxf(s, 1e-24f)) : 0.f;
    }
    __syncthreads();

    for (int idx = tid; idx < 1792; idx += blockDim.x) {
        int lane = idx & 31, f = idx >> 5;
        int nt = f % 7, ks = f / 7;
        int g = lane >> 2, q = lane & 3;
        int l = nt * 8 + g;
        uint2 o = make_uint2(0u, 0u);
        if (l < L_DIM) {
            float nrm = knorm[l];
            int k0 = ks * 16 + 2 * q;
            o.x = packhf(keys[l * C_DIM + k0]     * nrm,
                         keys[l * C_DIM + k0 + 1] * nrm);
            o.y = packhf(keys[l * C_DIM + k0 + 8]     * nrm,
                         keys[l * C_DIM + k0 + 8 + 1] * nrm);
        }
        g_kfrag2[idx] = o;
    }
    for (int idx = tid; idx < 1536; idx += blockDim.x) {
        int lane = idx & 31, f = idx >> 5;
        int nt = f & 15, ks = f >> 4;
        int g = lane >> 2, q = lane & 3;
        int n = nt * 8 + g;
        int k0 = ks * 16 + 2 * q;
        int k1 = k0 + 8;
        uint2 o;
        o.x = packhf(values[k0 * C_DIM + n], values[(k0 + 1) * C_DIM + n]);
        o.y = packhf(values[k1 * C_DIM + n], values[(k1 + 1) * C_DIM + n]);
        g_vfrag2[idx] = o;
    }
    for (int idx = tid; idx < 512; idx += blockDim.x) {
        int lane = idx & 31, nt = idx >> 5;
        int g = lane >> 2, q = lane & 3;
        int n = nt * 8 + g;
        int k0 = 48 + 2 * q;
        float a0 = (k0     < L_DIM) ? values[k0 * C_DIM + n]       : 0.f;
        float a1 = (k0 + 1 < L_DIM) ? values[(k0 + 1) * C_DIM + n] : 0.f;
        g_vfrag3[idx] = packhf(a0, a1);
    }
}

// ---------------------------------------------------------------- main
__global__ void __launch_bounds__(256, 3)
memmod_kernel(const float* __restrict__ x, float* __restrict__ out) {
    extern __shared__ float smem[];
    uint32_t* sm32 = (uint32_t*)smem;

    const int tid  = threadIdx.x;
    const int wid  = tid >> 5;
    const int lane = tid & 31;
    const int g    = lane >> 2;
    const int q    = lane & 3;
    const int b    = blockIdx.y;

    // copy baked fragment images into smem (28 KB, once)
    {
        const uint4* s1 = (const uint4*)g_kfrag2;
        const uint4* s2 = (const uint4*)g_vfrag2;
        const uint4* s3 = (const uint4*)g_vfrag3;
        uint4* d1 = (uint4*)(sm32 + KF_OFF32);
        uint4* d2 = (uint4*)(sm32 + VF2_OFF32);
        uint4* d3 = (uint4*)(sm32 + VF3_OFF32);
        for (int i = tid; i < 896; i += 256) d1[i] = s1[i];
        for (int i = tid; i < 768; i += 256) d2[i] = s2[i];
        if (tid < 128) d3[tid] = s3[tid];
    }
    __syncthreads();   // only barrier in the kernel

    const float* xb = x   + (size_t)b * C_DIM * HW_DIM;
    float*       ob = out + (size_t)b * C_DIM * HW_DIM;

    const int m0   = wid * 16;
    const int row0 = m0 + g;
    const int row1 = m0 + g + 8;

    const uint2*    kf2 = (const uint2*)(sm32 + KF_OFF32);
    const uint2*    vf2 = (const uint2*)(sm32 + VF2_OFF32);
    const uint32_t* vf3 = sm32 + VF3_OFF32;

    const int tile0 = blockIdx.x * TILES_PER_CTA;

    for (int t = 0; t < TILES_PER_CTA; t++) {
        const int n0 = (tile0 + t) * TILE_PX;
        const float* xp0 = xb + n0 + row0;
        const float* xp1 = xb + n0 + row1;

        // ---- L2 prefetch of next tile's x slice (1 line per channel) ----
        if (t + 1 < TILES_PER_CTA) {
            const float* xnext = xb + (size_t)(n0 + TILE_PX + m0);
            #pragma unroll
            for (int i = 0; i < 4; i++) {
                const float* pf = xnext + (size_t)(i * 32 + lane) * HW_DIM;
                asm volatile("prefetch.global.L2 [%0];" :: "l"(pf));
            }
        }

        // ---- phase A: load + ssq + pack-early to axf (no MMA inside) ----
        // holds 32 u32 frags instead of 64 floats -> fits 85-reg budget while
        // letting ptxas software-pipeline the loads (MLP ~16-24)
        uint32_t axf[8][4];
        float ssq0 = 0.f, ssq1 = 0.f;
        #pragma unroll
        for (int ks = 0; ks < 8; ks++) {
            const size_t c0 = (size_t)(16 * ks + 2 * q) * HW_DIM;
            float v0 = xp0[c0];
            float v1 = xp0[c0 + HW_DIM];
            float v2 = xp1[c0];
            float v3 = xp1[c0 + HW_DIM];
            float v4 = xp0[c0 + 8 * HW_DIM];
            float v5 = xp0[c0 + 9 * HW_DIM];
            float v6 = xp1[c0 + 8 * HW_DIM];
            float v7 = xp1[c0 + 9 * HW_DIM];
            ssq0 += v0 * v0 + v1 * v1 + v4 * v4 + v5 * v5;
            ssq1 += v2 * v2 + v3 * v3 + v6 * v6 + v7 * v7;
            axf[ks][0] = packhf(v0, v1);
            axf[ks][1] = packhf(v2, v3);
            axf[ks][2] = packhf(v4, v5);
            axf[ks][3] = packhf(v6, v7);
        }

        // quad reduce over q (lanes xor 1, 2 share the same row)
        ssq0 += __shfl_xor_sync(0xffffffffu, ssq0, 1);
        ssq0 += __shfl_xor_sync(0xffffffffu, ssq0, 2);
        ssq1 += __shfl_xor_sync(0xffffffffu, ssq1, 1);
        ssq1 += __shfl_xor_sync(0xffffffffu, ssq1, 2);
        float rn0 = rsqrtf(fmaxf(ssq0, 1e-24f));
        float rn1 = rsqrtf(fmaxf(ssq1, 1e-24f));

        // ---- phase B: GEMM1 logits[16px x 56slots], single-pass fp16 ----
        float acc1[7][4];
        #pragma unroll
        for (int nt = 0; nt < 7; nt++)
            #pragma unroll
            for (int i = 0; i < 4; i++) acc1[nt][i] = 0.f;

        #pragma unroll
        for (int ks = 0; ks < 8; ks++) {
            #pragma unroll
            for (int nt = 0; nt < 7; nt++) {
                uint2 bb = kf2[(ks * 7 + nt) * 32 + lane];
                mma_f16(acc1[nt], axf[ks], (const uint32_t*)&bb, acc1[nt]);
            }
        }

        // ---- softmax over 56 slots (quad-distributed), fp32 ----
        float mx0 = -1e30f, mx1 = -1e30f;
        #pragma unroll
        for (int nt = 0; nt < 7; nt++) {
            int l0 = nt * 8 + 2 * q, l1 = l0 + 1;
            acc1[nt][0] = (l0 < L_DIM) ? acc1[nt][0] * rn0 : -1e30f;
            acc1[nt][1] = (l1 < L_DIM) ? acc1[nt][1] * rn0 : -1e30f;
            acc1[nt][2] = (l0 < L_DIM) ? acc1[nt][2] * rn1 : -1e30f;
            acc1[nt][3] = (l1 < L_DIM) ? acc1[nt][3] * rn1 : -1e30f;
            mx0 = fmaxf(mx0, fmaxf(acc1[nt][0], acc1[nt][1]));
            mx1 = fmaxf(mx1, fmaxf(acc1[nt][2], acc1[nt][3]));
        }
        mx0 = fmaxf(mx0, __shfl_xor_sync(0xffffffffu, mx0, 1));
        mx0 = fmaxf(mx0, __shfl_xor_sync(0xffffffffu, mx0, 2));
        mx1 = fmaxf(mx1, __shfl_xor_sync(0xffffffffu, mx1, 1));
        mx1 = fmaxf(mx1, __shfl_xor_sync(0xffffffffu, mx1, 2));
        float s0 = 0.f, s1 = 0.f;
        #pragma unroll
        for (int nt = 0; nt < 7; nt++) {
            acc1[nt][0] = __expf(acc1[nt][0] - mx0);
            acc1[nt][1] = __expf(acc1[nt][1] - mx0);
            acc1[nt][2] = __expf(acc1[nt][2] - mx1);
            acc1[nt][3] = __expf(acc1[nt][3] - mx1);
            s0 += acc1[nt][0] + acc1[nt][1];
            s1 += acc1[nt][2] + acc1[nt][3];
        }
        s0 += __shfl_xor_sync(0xffffffffu, s0, 1);
        s0 += __shfl_xor_sync(0xffffffffu, s0, 2);
        s1 += __shfl_xor_sync(0xffffffffu, s1, 1);
        s1 += __shfl_xor_sync(0xffffffffu, s1, 2);
        float inv0 = 1.f / s0, inv1 = 1.f / s1;

        // weights -> GEMM2 A-frags, fp16 hi/lo split (22-bit effective)
        uint32_t wh[3][4], wl[3][4];
        #pragma unroll
        for (int ks = 0; ks < 3; ks++) {
            int ntA = 2 * ks, ntB = 2 * ks + 1;
            split2h(acc1[ntA][0] * inv0, acc1[ntA][1] * inv0, wh[ks][0], wl[ks][0]);
            split2h(acc1[ntA][2] * inv1, acc1[ntA][3] * inv1, wh[ks][1], wl[ks][1]);
            split2h(acc1[ntB][0] * inv0, acc1[ntB][1] * inv0, wh[ks][2], wl[ks][2]);
            split2h(acc1[ntB][2] * inv1, acc1[ntB][3] * inv1, wh[ks][3], wl[ks][3]);
        }
        uint32_t wh3[2], wl3[2];
        split2h(acc1[6][0] * inv0, acc1[6][1] * inv0, wh3[0], wl3[0]);
        split2h(acc1[6][2] * inv1, acc1[6][3] * inv1, wh3[1], wl3[1]);

        // ---- GEMM2: 2-pass (wh + wl) x single-fp16 V, two halves ----
        #pragma unroll
        for (int half = 0; half < 2; half++) {
            float acc2[8][4];
            #pragma unroll
            for (int nt = 0; nt < 8; nt++)
                #pragma unroll
                for (int i = 0; i < 4; i++) acc2[nt][i] = 0.f;

            #pragma unroll
            for (int nt = 0; nt < 8; nt++) {
                int ntg = half * 8 + nt;
                #pragma unroll
                for (int ks = 0; ks < 3; ks++) {
                    uint2 v = vf2[(ks * 16 + ntg) * 32 + lane];
                    mma_f16(acc2[nt], wh[ks], (const uint32_t*)&v, acc2[nt]);
                    mma_f16(acc2[nt], wl[ks], (const uint32_t*)&v, acc2[nt]);
                }
                uint32_t v3 = vf3[ntg * 32 + lane];
                mma_f16_k8(acc2[nt], wh3[0], wh3[1], v3, acc2[nt]);
                mma_f16_k8(acc2[nt], wl3[0], wl3[1], v3, acc2[nt]);
            }
            #pragma unroll
            for (int nt = 0; nt < 8; nt++) {
                int c0 = (half * 8 + nt) * 8 + 2 * q;
                size_t base = (size_t)c0 * HW_DIM + n0;
                __stcs(&ob[base + row0],          acc2[nt][0]);
                __stcs(&ob[base + HW_DIM + row0], acc2[nt][1]);
                __stcs(&ob[base + row1],          acc2[nt][2]);
                __stcs(&ob[base + HW_DIM + row1], acc2[nt][3]);
            }
        }
    }
}

// ---------------------------------------------------------------- launcher
extern "C" void kernel_launch(void* const* d_in, const int* in_sizes, int n_in,
                              void* d_out, int out_size) {
    const float* x      = (const float*)d_in[0];
    const float* keys   = (const float*)d_in[1];
    const float* values = (const float*)d_in[2];
    float* out = (float*)d_out;

    cudaFuncSetAttribute(memmod_kernel,
                         cudaFuncAttributeMaxDynamicSharedMemorySize, SMEM_BYTES);

    prep_kernel<<<1, 256>>>(keys, values);
    dim3 grid(HW_DIM / (TILES_PER_CTA * TILE_PX), B_DIM);
    memmod_kernel<<<grid, 256, SMEM_BYTES>>>(x, out);
}

// round 16
// speedup vs baseline: 1.1356x; 1.1356x over previous
#include <cuda_runtime.h>
#include <cuda_fp16.h>
#include <stdint.h>

#define B_DIM 64
#define C_DIM 128
#define HW_DIM 16384
#define L_DIM 50
#define TILES_PER_CTA 8
#define TILE_PX 128

// shared memory: fragment images only (u32 units)
#define KFP_OFF32  0                       // 768 uint4  = 3072 u32 (nt pairs)
#define KFS_OFF32  3072                    // 256 uint2  = 512 u32  (nt 6)
#define VFP_OFF32  3584                    // 512 uint4  = 2048 u32 (ks 0,1)
#define VFS2_OFF32 5632                    // 512 uint2  = 1024 u32 (ks 2)
#define VF3_OFF32  6656                    // 512 u32              (ks 3 r0)
#define SMEM_U32   7168
#define SMEM_BYTES (SMEM_U32 * 4)          // 28672

static __device__ __align__(16) uint4    g_kfp[768];   // 8 ks x 3 ntpair x 32
static __device__ __align__(16) uint2    g_kfs[256];   // 8 ks x 32 (nt=6)
static __device__ __align__(16) uint4    g_vfp[512];   // 16 nt x 32 (ks0+ks1)
static __device__ __align__(16) uint2    g_vfs2[512];  // 16 nt x 32 (ks2)
static __device__ __align__(16) uint32_t g_vf3[512];   // 16 nt x 32 (ks3 r0)

// ---------------------------------------------------------------- helpers
__device__ __forceinline__ uint32_t packhf(float lo, float hi) {
    __half2 t = __floats2half2_rn(lo, hi);
    return *(uint32_t*)&t;
}
__device__ __forceinline__ void split2h(float a, float b, uint32_t& hi, uint32_t& lo) {
    __half ha = __float2half_rn(a);
    __half hb = __float2half_rn(b);
    hi = ((uint32_t)__half_as_ushort(hb) << 16) | (uint32_t)__half_as_ushort(ha);
    lo = packhf(a - __half2float(ha), b - __half2float(hb));
}
__device__ __forceinline__ void mma_f16(float* d, const uint32_t* a,
                                        uint32_t b0, uint32_t b1, const float* c) {
    asm volatile(
        "mma.sync.aligned.m16n8k16.row.col.f32.f16.f16.f32 "
        "{%0,%1,%2,%3}, {%4,%5,%6,%7}, {%8,%9}, {%10,%11,%12,%13};"
        : "=f"(d[0]), "=f"(d[1]), "=f"(d[2]), "=f"(d[3])
        : "r"(a[0]), "r"(a[1]), "r"(a[2]), "r"(a[3]),
          "r"(b0), "r"(b1),
          "f"(c[0]), "f"(c[1]), "f"(c[2]), "f"(c[3]));
}
__device__ __forceinline__ void mma_f16_k8(float* d, uint32_t a0, uint32_t a1,
                                           uint32_t b0, const float* c) {
    asm volatile(
        "mma.sync.aligned.m16n8k8.row.col.f32.f16.f16.f32 "
        "{%0,%1,%2,%3}, {%4,%5}, {%6}, {%7,%8,%9,%10};"
        : "=f"(d[0]), "=f"(d[1]), "=f"(d[2]), "=f"(d[3])
        : "r"(a0), "r"(a1), "r"(b0),
          "f"(c[0]), "f"(c[1]), "f"(c[2]), "f"(c[3]));
}

// ---------------------------------------------------- prep (fp16 images)
__global__ void prep_kernel(const float* __restrict__ keys,
                            const float* __restrict__ values) {
    __shared__ float knorm[64];
    int tid = threadIdx.x;
    if (tid < 64) {
        float s = 0.f;
        if (tid < L_DIM) {
            for (int c = 0; c < C_DIM; c++) {
                float v = keys[tid * C_DIM + c];
                s += v * v;
            }
        }
        knorm[tid] = (tid < L_DIM) ? rsqrtf(fmaxf(s, 1e-24f)) : 0.f;
    }
    __syncthreads();

    // kfp: nt pairs (0,1),(2,3),(4,5) per ks
    for (int idx = tid; idx < 768; idx += blockDim.x) {
        int lane = idx & 31, f = idx >> 5;
        int p = f % 3, ks = f / 3;
        int g = lane >> 2, q = lane & 3;
        int k0 = ks * 16 + 2 * q;
        uint4 o = make_uint4(0u, 0u, 0u, 0u);
        int l0 = (2 * p) * 8 + g;
        if (l0 < L_DIM) {
            float nrm = knorm[l0];
            o.x = packhf(keys[l0 * C_DIM + k0] * nrm, keys[l0 * C_DIM + k0 + 1] * nrm);
            o.y = packhf(keys[l0 * C_DIM + k0 + 8] * nrm, keys[l0 * C_DIM + k0 + 9] * nrm);
        }
        int l1 = (2 * p + 1) * 8 + g;
        if (l1 < L_DIM) {
            float nrm = knorm[l1];
            o.z = packhf(keys[l1 * C_DIM + k0] * nrm, keys[l1 * C_DIM + k0 + 1] * nrm);
            o.w = packhf(keys[l1 * C_DIM + k0 + 8] * nrm, keys[l1 * C_DIM + k0 + 9] * nrm);
        }
        g_kfp[idx] = o;
    }
    // kfs: nt = 6 (slots 48..55, all < 50 only partially)
    for (int idx = tid; idx < 256; idx += blockDim.x) {
        int lane = idx & 31, ks = idx >> 5;
        int g = lane >> 2, q = lane & 3;
        int l = 48 + g;
        int k0 = ks * 16 + 2 * q;
        uint2 o = make_uint2(0u, 0u);
        if (l < L_DIM) {
            float nrm = knorm[l];
            o.x = packhf(keys[l * C_DIM + k0] * nrm, keys[l * C_DIM + k0 + 1] * nrm);
            o.y = packhf(keys[l * C_DIM + k0 + 8] * nrm, keys[l * C_DIM + k0 + 9] * nrm);
        }
        g_kfs[idx] = o;
    }
    // vfp: ks 0 and 1 per n-tile (slots 0..31, all real)
    for (int idx = tid; idx < 512; idx += blockDim.x) {
        int lane = idx & 31, nt = idx >> 5;
        int g = lane >> 2, q = lane & 3;
        int n = nt * 8 + g;
        uint4 o;
        {
            int k0 = 2 * q, k1 = k0 + 8;
            o.x = packhf(values[k0 * C_DIM + n], values[(k0 + 1) * C_DIM + n]);
            o.y = packhf(values[k1 * C_DIM + n], values[(k1 + 1) * C_DIM + n]);
        }
        {
            int k0 = 16 + 2 * q, k1 = k0 + 8;
            o.z = packhf(values[k0 * C_DIM + n], values[(k0 + 1) * C_DIM + n]);
            o.w = packhf(values[k1 * C_DIM + n], values[(k1 + 1) * C_DIM + n]);
        }
        g_vfp[idx] = o;
    }
    // vfs2: ks = 2 (slots 32..47, all real)
    for (int idx = tid; idx < 512; idx += blockDim.x) {
        int lane = idx & 31, nt = idx >> 5;
        int g = lane >> 2, q = lane & 3;
        int n = nt * 8 + g;
        int k0 = 32 + 2 * q, k1 = k0 + 8;
        uint2 o;
        o.x = packhf(values[k0 * C_DIM + n], values[(k0 + 1) * C_DIM + n]);
        o.y = packhf(values[k1 * C_DIM + n], values[(k1 + 1) * C_DIM + n]);
        g_vfs2[idx] = o;
    }
    // vf3: ks = 3 r0 only (slots 48..55; 50+ are zero)
    for (int idx = tid; idx < 512; idx += blockDim.x) {
        int lane = idx & 31, nt = idx >> 5;
        int g = lane >> 2, q = lane & 3;
        int n = nt * 8 + g;
        int k0 = 48 + 2 * q;
        float a0 = (k0     < L_DIM) ? values[k0 * C_DIM + n]       : 0.f;
        float a1 = (k0 + 1 < L_DIM) ? values[(k0 + 1) * C_DIM + n] : 0.f;
        g_vf3[idx] = packhf(a0, a1);
    }
}

// ---------------------------------------------------------------- main
__global__ void __launch_bounds__(256, 2)
memmod_kernel(const float* __restrict__ x, float* __restrict__ out) {
    extern __shared__ float smem[];
    uint32_t* sm32 = (uint32_t*)smem;

    const int tid  = threadIdx.x;
    const int wid  = tid >> 5;
    const int lane = tid & 31;
    const int g    = lane >> 2;
    const int q    = lane & 3;
    const int b    = blockIdx.y;

    // copy baked fragment images into smem (28 KB, once)
    {
        const uint4* s1 = (const uint4*)g_kfp;    // 768 uint4
        const uint4* s2 = (const uint4*)g_kfs;    // 128 uint4
        const uint4* s3 = (const uint4*)g_vfp;    // 512 uint4
        const uint4* s4 = (const uint4*)g_vfs2;   // 256 uint4
        const uint4* s5 = (const uint4*)g_vf3;    // 128 uint4
        uint4* d1 = (uint4*)(sm32 + KFP_OFF32);
        uint4* d2 = (uint4*)(sm32 + KFS_OFF32);
        uint4* d3 = (uint4*)(sm32 + VFP_OFF32);
        uint4* d4 = (uint4*)(sm32 + VFS2_OFF32);
        uint4* d5 = (uint4*)(sm32 + VF3_OFF32);
        for (int i = tid; i < 768; i += 256) d1[i] = s1[i];
        for (int i = tid; i < 512; i += 256) d3[i] = s3[i];
        if (tid < 128) d2[tid] = s2[tid];
        if (tid < 256) d4[tid] = s4[tid];
        if (tid < 128) d5[tid] = s5[tid];
    }
    __syncthreads();   // only barrier in the kernel

    const float* xb = x   + (size_t)b * C_DIM * HW_DIM;
    float*       ob = out + (size_t)b * C_DIM * HW_DIM;

    const int m0   = wid * 16;
    const int row0 = m0 + g;
    const int row1 = m0 + g + 8;

    const uint4*    kfp  = (const uint4*)(sm32 + KFP_OFF32);
    const uint2*    kfs  = (const uint2*)(sm32 + KFS_OFF32);
    const uint4*    vfp  = (const uint4*)(sm32 + VFP_OFF32);
    const uint2*    vfs2 = (const uint2*)(sm32 + VFS2_OFF32);
    const uint32_t* vf3  = sm32 + VF3_OFF32;

    const int tile0 = blockIdx.x * TILES_PER_CTA;

    for (int t = 0; t < TILES_PER_CTA; t++) {
        const int n0 = (tile0 + t) * TILE_PX;

        // ---- A-fragments straight from gmem (front-batched LDG.32, MLP~64) ----
        const float* xp0 = xb + n0 + row0;
        const float* xp1 = xb + n0 + row1;
        float xv[8][8];
        #pragma unroll
        for (int ks = 0; ks < 8; ks++) {
            const size_t c0 = (size_t)(16 * ks + 2 * q) * HW_DIM;
            xv[ks][0] = xp0[c0];
            xv[ks][1] = xp0[c0 + HW_DIM];
            xv[ks][2] = xp1[c0];
            xv[ks][3] = xp1[c0 + HW_DIM];
            xv[ks][4] = xp0[c0 + 8 * HW_DIM];
            xv[ks][5] = xp0[c0 + 9 * HW_DIM];
            xv[ks][6] = xp1[c0 + 8 * HW_DIM];
            xv[ks][7] = xp1[c0 + 9 * HW_DIM];
        }

        // ---- L2 prefetch of next tile's x slice (1 line per channel) ----
        if (t + 1 < TILES_PER_CTA) {
            const float* xnext = xb + (size_t)(n0 + TILE_PX + m0);
            #pragma unroll
            for (int i = 0; i < 4; i++) {
                const float* pf = xnext + (size_t)(i * 32 + lane) * HW_DIM;
                asm volatile("prefetch.global.L2 [%0];" :: "l"(pf));
            }
        }

        float ssq0 = 0.f, ssq1 = 0.f;
        uint32_t axf[8][4];
        #pragma unroll
        for (int ks = 0; ks < 8; ks++) {
            ssq0 += xv[ks][0] * xv[ks][0] + xv[ks][1] * xv[ks][1]
                  + xv[ks][4] * xv[ks][4] + xv[ks][5] * xv[ks][5];
            ssq1 += xv[ks][2] * xv[ks][2] + xv[ks][3] * xv[ks][3]
                  + xv[ks][6] * xv[ks][6] + xv[ks][7] * xv[ks][7];
            axf[ks][0] = packhf(xv[ks][0], xv[ks][1]);
            axf[ks][1] = packhf(xv[ks][2], xv[ks][3]);
            axf[ks][2] = packhf(xv[ks][4], xv[ks][5]);
            axf[ks][3] = packhf(xv[ks][6], xv[ks][7]);
        }
        // quad reduce over q (lanes xor 1, 2 share the same row)
        ssq0 += __shfl_xor_sync(0xffffffffu, ssq0, 1);
        ssq0 += __shfl_xor_sync(0xffffffffu, ssq0, 2);
        ssq1 += __shfl_xor_sync(0xffffffffu, ssq1, 1);
        ssq1 += __shfl_xor_sync(0xffffffffu, ssq1, 2);
        float rn0 = rsqrtf(fmaxf(ssq0, 1e-24f));
        float rn1 = rsqrtf(fmaxf(ssq1, 1e-24f));

        // ---- GEMM1: logits[16px x 56slots], paired LDS.128 B loads ----
        float acc1[7][4];
        #pragma unroll
        for (int nt = 0; nt < 7; nt++)
            #pragma unroll
            for (int i = 0; i < 4; i++) acc1[nt][i] = 0.f;

        #pragma unroll
        for (int ks = 0; ks < 8; ks++) {
            #pragma unroll
            for (int p = 0; p < 3; p++) {
                uint4 kk = kfp[(ks * 3 + p) * 32 + lane];
                mma_f16(acc1[2 * p],     axf[ks], kk.x, kk.y, acc1[2 * p]);
                mma_f16(acc1[2 * p + 1], axf[ks], kk.z, kk.w, acc1[2 * p + 1]);
            }
            uint2 k6 = kfs[ks * 32 + lane];
            mma_f16(acc1[6], axf[ks], k6.x, k6.y, acc1[6]);
        }

        // ---- softmax over 56 slots (quad-distributed), fp32 ----
        float mx0 = -1e30f, mx1 = -1e30f;
        #pragma unroll
        for (int nt = 0; nt < 7; nt++) {
            int l0 = nt * 8 + 2 * q, l1 = l0 + 1;
            acc1[nt][0] = (l0 < L_DIM) ? acc1[nt][0] * rn0 : -1e30f;
            acc1[nt][1] = (l1 < L_DIM) ? acc1[nt][1] * rn0 : -1e30f;
            acc1[nt][2] = (l0 < L_DIM) ? acc1[nt][2] * rn1 : -1e30f;
            acc1[nt][3] = (l1 < L_DIM) ? acc1[nt][3] * rn1 : -1e30f;
            mx0 = fmaxf(mx0, fmaxf(acc1[nt][0], acc1[nt][1]));
            mx1 = fmaxf(mx1, fmaxf(acc1[nt][2], acc1[nt][3]));
        }
        mx0 = fmaxf(mx0, __shfl_xor_sync(0xffffffffu, mx0, 1));
        mx0 = fmaxf(mx0, __shfl_xor_sync(0xffffffffu, mx0, 2));
        mx1 = fmaxf(mx1, __shfl_xor_sync(0xffffffffu, mx1, 1));
        mx1 = fmaxf(mx1, __shfl_xor_sync(0xffffffffu, mx1, 2));
        float s0 = 0.f, s1 = 0.f;
        #pragma unroll
        for (int nt = 0; nt < 7; nt++) {
            acc1[nt][0] = __expf(acc1[nt][0] - mx0);
            acc1[nt][1] = __expf(acc1[nt][1] - mx0);
            acc1[nt][2] = __expf(acc1[nt][2] - mx1);
            acc1[nt][3] = __expf(acc1[nt][3] - mx1);
            s0 += acc1[nt][0] + acc1[nt][1];
            s1 += acc1[nt][2] + acc1[nt][3];
        }
        s0 += __shfl_xor_sync(0xffffffffu, s0, 1);
        s0 += __shfl_xor_sync(0xffffffffu, s0, 2);
        s1 += __shfl_xor_sync(0xffffffffu, s1, 1);
        s1 += __shfl_xor_sync(0xffffffffu, s1, 2);
        float inv0 = 1.f / s0, inv1 = 1.f / s1;

        // weights -> GEMM2 A-frags, fp16 hi/lo split (22-bit effective)
        uint32_t wh[3][4], wl[3][4];
        #pragma unroll
        for (int ks = 0; ks < 3; ks++) {
            int ntA = 2 * ks, ntB = 2 * ks + 1;
            split2h(acc1[ntA][0] * inv0, acc1[ntA][1] * inv0, wh[ks][0], wl[ks][0]);
            split2h(acc1[ntA][2] * inv1, acc1[ntA][3] * inv1, wh[ks][1], wl[ks][1]);
            split2h(acc1[ntB][0] * inv0, acc1[ntB][1] * inv0, wh[ks][2], wl[ks][2]);
            split2h(acc1[ntB][2] * inv1, acc1[ntB][3] * inv1, wh[ks][3], wl[ks][3]);
        }
        uint32_t wh3[2], wl3[2];
        split2h(acc1[6][0] * inv0, acc1[6][1] * inv0, wh3[0], wl3[0]);
        split2h(acc1[6][2] * inv1, acc1[6][3] * inv1, wh3[1], wl3[1]);

        // ---- GEMM2: 2-pass (wh + wl), paired LDS.128 V loads, two halves ----
        #pragma unroll
        for (int half = 0; half < 2; half++) {
            float acc2[8][4];
            #pragma unroll
            for (int nt = 0; nt < 8; nt++)
                #pragma unroll
                for (int i = 0; i < 4; i++) acc2[nt][i] = 0.f;

            #pragma unroll
            for (int nt = 0; nt < 8; nt++) {
                int ntg = half * 8 + nt;
                uint4 v01 = vfp[ntg * 32 + lane];
                mma_f16(acc2[nt], wh[0], v01.x, v01.y, acc2[nt]);
                mma_f16(acc2[nt], wl[0], v01.x, v01.y, acc2[nt]);
                mma_f16(acc2[nt], wh[1], v01.z, v01.w, acc2[nt]);
                mma_f16(acc2[nt], wl[1], v01.z, v01.w, acc2[nt]);
                uint2 v2 = vfs2[ntg * 32 + lane];
                mma_f16(acc2[nt], wh[2], v2.x, v2.y, acc2[nt]);
                mma_f16(acc2[nt], wl[2], v2.x, v2.y, acc2[nt]);
                uint32_t v3 = vf3[ntg * 32 + lane];
                mma_f16_k8(acc2[nt], wh3[0], wh3[1], v3, acc2[nt]);
                mma_f16_k8(acc2[nt], wl3[0], wl3[1], v3, acc2[nt]);
            }
            #pragma unroll
            for (int nt = 0; nt < 8; nt++) {
                int c0 = (half * 8 + nt) * 8 + 2 * q;
                size_t base = (size_t)c0 * HW_DIM + n0;
                __stcs(&ob[base + row0],          acc2[nt][0]);
                __stcs(&ob[base + HW_DIM + row0], acc2[nt][1]);
                __stcs(&ob[base + row1],          acc2[nt][2]);
                __stcs(&ob[base + HW_DIM + row1], acc2[nt][3]);
            }
        }
    }
}

// ---------------------------------------------------------------- launcher
extern "C" void kernel_launch(void* const* d_in, const int* in_sizes, int n_in,
                              void* d_out, int out_size) {
    const float* x      = (const float*)d_in[0];
    const float* keys   = (const float*)d_in[1];
    const float* values = (const float*)d_in[2];
    float* out = (float*)d_out;

    cudaFuncSetAttribute(memmod_kernel,
                         cudaFuncAttributeMaxDynamicSharedMemorySize, SMEM_BYTES);

    prep_kernel<<<1, 256>>>(keys, values);
    dim3 grid(HW_DIM / (TILES_PER_CTA * TILE_PX), B_DIM);
    memmod_kernel<<<grid, 256, SMEM_BYTES>>>(x, out);
}

// round 17
// speedup vs baseline: 1.2048x; 1.0609x over previous
#include <cuda_runtime.h>
#include <cuda_fp16.h>
#include <stdint.h>

#define B_DIM 64
#define C_DIM 128
#define HW_DIM 16384
#define L_DIM 50
#define TILES_PER_CTA 8
#define TILE_PX 128

// shared memory: fragment images only (u32 units)
#define KF_OFF32  0                        // 1792 uint2 = 3584 u32
#define VF2_OFF32 3584                     // 1536 uint2 = 3072 u32
#define VF3_OFF32 6656                     // 512 u32
#define SMEM_U32  7168
#define SMEM_BYTES (SMEM_U32 * 4)          // 28672

static __device__ __align__(16) uint2    g_kfrag2[1792];  // 8 ks x 7 nt x 32 (fp16)
static __device__ __align__(16) uint2    g_vfrag2[1536];  // 3 ks x 16 nt x 32 (fp16)
static __device__ __align__(16) uint32_t g_vfrag3[512];   // 16 nt x 32 (ks=3 r0)

// ---------------------------------------------------------------- helpers
__device__ __forceinline__ uint32_t packhf(float lo, float hi) {
    __half2 t = __floats2half2_rn(lo, hi);
    return *(uint32_t*)&t;
}
__device__ __forceinline__ void split2h(float a, float b, uint32_t& hi, uint32_t& lo) {
    __half ha = __float2half_rn(a);
    __half hb = __float2half_rn(b);
    hi = ((uint32_t)__half_as_ushort(hb) << 16) | (uint32_t)__half_as_ushort(ha);
    lo = packhf(a - __half2float(ha), b - __half2float(hb));
}
__device__ __forceinline__ void mma_f16(float* d, const uint32_t* a,
                                        const uint32_t* b, const float* c) {
    asm volatile(
        "mma.sync.aligned.m16n8k16.row.col.f32.f16.f16.f32 "
        "{%0,%1,%2,%3}, {%4,%5,%6,%7}, {%8,%9}, {%10,%11,%12,%13};"
        : "=f"(d[0]), "=f"(d[1]), "=f"(d[2]), "=f"(d[3])
        : "r"(a[0]), "r"(a[1]), "r"(a[2]), "r"(a[3]),
          "r"(b[0]), "r"(b[1]),
          "f"(c[0]), "f"(c[1]), "f"(c[2]), "f"(c[3]));
}
__device__ __forceinline__ void mma_f16_k8(float* d, uint32_t a0, uint32_t a1,
                                           uint32_t b0, const float* c) {
    asm volatile(
        "mma.sync.aligned.m16n8k8.row.col.f32.f16.f16.f32 "
        "{%0,%1,%2,%3}, {%4,%5}, {%6}, {%7,%8,%9,%10};"
        : "=f"(d[0]), "=f"(d[1]), "=f"(d[2]), "=f"(d[3])
        : "r"(a0), "r"(a1), "r"(b0),
          "f"(c[0]), "f"(c[1]), "f"(c[2]), "f"(c[3]));
}

// ---------------------------------------------------- prep (fp16 images)
__global__ void prep_kernel(const float* __restrict__ keys,
                            const float* __restrict__ values) {
    __shared__ float knorm[64];
    int tid = threadIdx.x;
    if (tid < 64) {
        float s = 0.f;
        if (tid < L_DIM) {
            for (int c = 0; c < C_DIM; c++) {
                float v = keys[tid * C_DIM + c];
                s += v * v;
            }
        }
        knorm[tid] = (tid < L_DIM) ? rsqrtf(fmaxf(s, 1e-24f)) : 0.f;
    }
    __syncthreads();

    for (int idx = tid; idx < 1792; idx += blockDim.x) {
        int lane = idx & 31, f = idx >> 5;
        int nt = f % 7, ks = f / 7;
        int g = lane >> 2, q = lane & 3;
        int l = nt * 8 + g;
        uint2 o = make_uint2(0u, 0u);
        if (l < L_DIM) {
            float nrm = knorm[l];
            int k0 = ks * 16 + 2 * q;
            o.x = packhf(keys[l * C_DIM + k0]     * nrm,
                         keys[l * C_DIM + k0 + 1] * nrm);
            o.y = packhf(keys[l * C_DIM + k0 + 8]     * nrm,
                         keys[l * C_DIM + k0 + 8 + 1] * nrm);
        }
        g_kfrag2[idx] = o;
    }
    for (int idx = tid; idx < 1536; idx += blockDim.x) {
        int lane = idx & 31, f = idx >> 5;
        int nt = f & 15, ks = f >> 4;
        int g = lane >> 2, q = lane & 3;
        int n = nt * 8 + g;
        int k0 = ks * 16 + 2 * q;
        int k1 = k0 + 8;
        uint2 o;
        o.x = packhf(values[k0 * C_DIM + n], values[(k0 + 1) * C_DIM + n]);
        o.y = packhf(values[k1 * C_DIM + n], values[(k1 + 1) * C_DIM + n]);
        g_vfrag2[idx] = o;
    }
    for (int idx = tid; idx < 512; idx += blockDim.x) {
        int lane = idx & 31, nt = idx >> 5;
        int g = lane >> 2, q = lane & 3;
        int n = nt * 8 + g;
        int k0 = 48 + 2 * q;
        float a0 = (k0     < L_DIM) ? values[k0 * C_DIM + n]       : 0.f;
        float a1 = (k0 + 1 < L_DIM) ? values[(k0 + 1) * C_DIM + n] : 0.f;
        g_vfrag3[idx] = packhf(a0, a1);
    }
}

// ---------------------------------------------------------------- main
__global__ void __launch_bounds__(256, 2)
memmod_kernel(const float* __restrict__ x, float* __restrict__ out) {
    extern __shared__ float smem[];
    uint32_t* sm32 = (uint32_t*)smem;

    const int tid  = threadIdx.x;
    const int wid  = tid >> 5;
    const int lane = tid & 31;
    const int g    = lane >> 2;
    const int q    = lane & 3;
    const int b    = blockIdx.y;

    const float* xb = x   + (size_t)b * C_DIM * HW_DIM;
    float*       ob = out + (size_t)b * C_DIM * HW_DIM;

    const int m0    = wid * 16;
    const int tile0 = blockIdx.x * TILES_PER_CTA;

    // ---- cold-start L2 prefetch of tile 0 (even warps; wid^1 shares lines) ----
    if (!(wid & 1)) {
        const float* x0 = xb + (size_t)(tile0 * TILE_PX + m0);
        #pragma unroll
        for (int i = 0; i < 4; i++) {
            const float* pf = x0 + (size_t)(i * 32 + lane) * HW_DIM;
            asm volatile("prefetch.global.L2 [%0];" :: "l"(pf));
        }
    }

    // copy baked fragment images into smem (28 KB, once) — covers prefetch trip
    {
        const uint4* s1 = (const uint4*)g_kfrag2;
        const uint4* s2 = (const uint4*)g_vfrag2;
        const uint4* s3 = (const uint4*)g_vfrag3;
        uint4* d1 = (uint4*)(sm32 + KF_OFF32);
        uint4* d2 = (uint4*)(sm32 + VF2_OFF32);
        uint4* d3 = (uint4*)(sm32 + VF3_OFF32);
        for (int i = tid; i < 896; i += 256) d1[i] = s1[i];
        for (int i = tid; i < 768; i += 256) d2[i] = s2[i];
        if (tid < 128) d3[tid] = s3[tid];
    }
    __syncthreads();   // only barrier in the kernel

    const int row0 = m0 + g;
    const int row1 = m0 + g + 8;

    const uint2*    kf2 = (const uint2*)(sm32 + KF_OFF32);
    const uint2*    vf2 = (const uint2*)(sm32 + VF2_OFF32);
    const uint32_t* vf3 = sm32 + VF3_OFF32;

    for (int t = 0; t < TILES_PER_CTA; t++) {
        const int n0 = (tile0 + t) * TILE_PX;

        // ---- A-fragments straight from gmem (front-batched LDG.32, MLP~64) ----
        const float* xp0 = xb + n0 + row0;
        const float* xp1 = xb + n0 + row1;
        float xv[8][8];
        #pragma unroll
        for (int ks = 0; ks < 8; ks++) {
            const size_t c0 = (size_t)(16 * ks + 2 * q) * HW_DIM;
            xv[ks][0] = xp0[c0];
            xv[ks][1] = xp0[c0 + HW_DIM];
            xv[ks][2] = xp1[c0];
            xv[ks][3] = xp1[c0 + HW_DIM];
            xv[ks][4] = xp0[c0 + 8 * HW_DIM];
            xv[ks][5] = xp0[c0 + 9 * HW_DIM];
            xv[ks][6] = xp1[c0 + 8 * HW_DIM];
            xv[ks][7] = xp1[c0 + 9 * HW_DIM];
        }

        // ---- L2 prefetch of next tile's x slice (even warps only) ----
        if (t + 1 < TILES_PER_CTA && !(wid & 1)) {
            const float* xnext = xb + (size_t)(n0 + TILE_PX + m0);
            #pragma unroll
            for (int i = 0; i < 4; i++) {
                const float* pf = xnext + (size_t)(i * 32 + lane) * HW_DIM;
                asm volatile("prefetch.global.L2 [%0];" :: "l"(pf));
            }
        }

        float ssq0 = 0.f, ssq1 = 0.f;
        uint32_t axf[8][4];
        #pragma unroll
        for (int ks = 0; ks < 8; ks++) {
            ssq0 += xv[ks][0] * xv[ks][0] + xv[ks][1] * xv[ks][1]
                  + xv[ks][4] * xv[ks][4] + xv[ks][5] * xv[ks][5];
            ssq1 += xv[ks][2] * xv[ks][2] + xv[ks][3] * xv[ks][3]
                  + xv[ks][6] * xv[ks][6] + xv[ks][7] * xv[ks][7];
            axf[ks][0] = packhf(xv[ks][0], xv[ks][1]);
            axf[ks][1] = packhf(xv[ks][2], xv[ks][3]);
            axf[ks][2] = packhf(xv[ks][4], xv[ks][5]);
            axf[ks][3] = packhf(xv[ks][6], xv[ks][7]);
        }
        // quad reduce over q (lanes xor 1, 2 share the same row)
        ssq0 += __shfl_xor_sync(0xffffffffu, ssq0, 1);
        ssq0 += __shfl_xor_sync(0xffffffffu, ssq0, 2);
        ssq1 += __shfl_xor_sync(0xffffffffu, ssq1, 1);
        ssq1 += __shfl_xor_sync(0xffffffffu, ssq1, 2);
        float rn0 = rsqrtf(fmaxf(ssq0, 1e-24f));
        float rn1 = rsqrtf(fmaxf(ssq1, 1e-24f));

        // ---- GEMM1: logits[16px x 56slots], single-pass fp16 ----
        float acc1[7][4];
        #pragma unroll
        for (int nt = 0; nt < 7; nt++)
            #pragma unroll
            for (int i = 0; i < 4; i++) acc1[nt][i] = 0.f;

        #pragma unroll
        for (int ks = 0; ks < 8; ks++) {
            #pragma unroll
            for (int nt = 0; nt < 7; nt++) {
                uint2 bb = kf2[(ks * 7 + nt) * 32 + lane];
                mma_f16(acc1[nt], axf[ks], (const uint32_t*)&bb, acc1[nt]);
            }
        }

        // ---- softmax over 56 slots (quad-distributed), fp32 ----
        float mx0 = -1e30f, mx1 = -1e30f;
        #pragma unroll
        for (int nt = 0; nt < 7; nt++) {
            int l0 = nt * 8 + 2 * q, l1 = l0 + 1;
            acc1[nt][0] = (l0 < L_DIM) ? acc1[nt][0] * rn0 : -1e30f;
            acc1[nt][1] = (l1 < L_DIM) ? acc1[nt][1] * rn0 : -1e30f;
            acc1[nt][2] = (l0 < L_DIM) ? acc1[nt][2] * rn1 : -1e30f;
            acc1[nt][3] = (l1 < L_DIM) ? acc1[nt][3] * rn1 : -1e30f;
            mx0 = fmaxf(mx0, fmaxf(acc1[nt][0], acc1[nt][1]));
            mx1 = fmaxf(mx1, fmaxf(acc1[nt][2], acc1[nt][3]));
        }
        mx0 = fmaxf(mx0, __shfl_xor_sync(0xffffffffu, mx0, 1));
        mx0 = fmaxf(mx0, __shfl_xor_sync(0xffffffffu, mx0, 2));
        mx1 = fmaxf(mx1, __shfl_xor_sync(0xffffffffu, mx1, 1));
        mx1 = fmaxf(mx1, __shfl_xor_sync(0xffffffffu, mx1, 2));
        float s0 = 0.f, s1 = 0.f;
        #pragma unroll
        for (int nt = 0; nt < 7; nt++) {
            acc1[nt][0] = __expf(acc1[nt][0] - mx0);
            acc1[nt][1] = __expf(acc1[nt][1] - mx0);
            acc1[nt][2] = __expf(acc1[nt][2] - mx1);
            acc1[nt][3] = __expf(acc1[nt][3] - mx1);
            s0 += acc1[nt][0] + acc1[nt][1];
            s1 += acc1[nt][2] + acc1[nt][3];
        }
        s0 += __shfl_xor_sync(0xffffffffu, s0, 1);
        s0 += __shfl_xor_sync(0xffffffffu, s0, 2);
        s1 += __shfl_xor_sync(0xffffffffu, s1, 1);
        s1 += __shfl_xor_sync(0xffffffffu, s1, 2);
        float inv0 = 1.f / s0, inv1 = 1.f / s1;

        // weights -> GEMM2 A-frags, fp16 hi/lo split (22-bit effective)
        uint32_t wh[3][4], wl[3][4];
        #pragma unroll
        for (int ks = 0; ks < 3; ks++) {
            int ntA = 2 * ks, ntB = 2 * ks + 1;
            split2h(acc1[ntA][0] * inv0, acc1[ntA][1] * inv0, wh[ks][0], wl[ks][0]);
            split2h(acc1[ntA][2] * inv1, acc1[ntA][3] * inv1, wh[ks][1], wl[ks][1]);
            split2h(acc1[ntB][0] * inv0, acc1[ntB][1] * inv0, wh[ks][2], wl[ks][2]);
            split2h(acc1[ntB][2] * inv1, acc1[ntB][3] * inv1, wh[ks][3], wl[ks][3]);
        }
        uint32_t wh3[2], wl3[2];
        split2h(acc1[6][0] * inv0, acc1[6][1] * inv0, wh3[0], wl3[0]);
        split2h(acc1[6][2] * inv1, acc1[6][3] * inv1, wh3[1], wl3[1]);

        // ---- GEMM2: 2-pass (wh + wl) x single-fp16 V, two halves ----
        #pragma unroll
        for (int half = 0; half < 2; half++) {
            float acc2[8][4];
            #pragma unroll
            for (int nt = 0; nt < 8; nt++)
                #pragma unroll
                for (int i = 0; i < 4; i++) acc2[nt][i] = 0.f;

            #pragma unroll
            for (int nt = 0; nt < 8; nt++) {
                int ntg = half * 8 + nt;
                #pragma unroll
                for (int ks = 0; ks < 3; ks++) {
                    uint2 v = vf2[(ks * 16 + ntg) * 32 + lane];
                    mma_f16(acc2[nt], wh[ks], (const uint32_t*)&v, acc2[nt]);
                    mma_f16(acc2[nt], wl[ks], (const uint32_t*)&v, acc2[nt]);
                }
                uint32_t v3 = vf3[ntg * 32 + lane];
                mma_f16_k8(acc2[nt], wh3[0], wh3[1], v3, acc2[nt]);
                mma_f16_k8(acc2[nt], wl3[0], wl3[1], v3, acc2[nt]);
            }
            #pragma unroll
            for (int nt = 0; nt < 8; nt++) {
                int c0 = (half * 8 + nt) * 8 + 2 * q;
                size_t base = (size_t)c0 * HW_DIM + n0;
                __stcs(&ob[base + row0],          acc2[nt][0]);
                __stcs(&ob[base + HW_DIM + row0], acc2[nt][1]);
                __stcs(&ob[base + row1],          acc2[nt][2]);
                __stcs(&ob[base + HW_DIM + row1], acc2[nt][3]);
            }
        }
    }
}

// ---------------------------------------------------------------- launcher
extern "C" void kernel_launch(void* const* d_in, const int* in_sizes, int n_in,
                              void* d_out, int out_size) {
    const float* x      = (const float*)d_in[0];
    const float* keys   = (const float*)d_in[1];
    const float* values = (const float*)d_in[2];
    float* out = (float*)d_out;

    cudaFuncSetAttribute(memmod_kernel,
                         cudaFuncAttributeMaxDynamicSharedMemorySize, SMEM_BYTES);

    prep_kernel<<<1, 256>>>(keys, values);
    dim3 grid(HW_DIM / (TILES_PER_CTA * TILE_PX), B_DIM);
    memmod_kernel<<<grid, 256, SMEM_BYTES>>>(x, out);
}